// round 3
// baseline (speedup 1.0000x reference)
#include <cuda_runtime.h>
#include <cuda_bf16.h>
#include <cstdint>

#define BATCH 32
#define SLEN  128
#define TLEN  64
#define VOC   32000
#define EMB   256
#define HID   512
#define G3    1536            // 3*HID
#define BT    (BATCH*TLEN)    // 2048 decoder rows
#define SB    (SLEN*BATCH)    // 4096 encoder rows

// ---------------- scratch (device globals; no allocation allowed) ----------
__device__ float g_WhhT[HID*G3];              // enc Whh transposed [k][3H]
__device__ float g_WhT [HID*G3];              // dec Wh  transposed
__device__ float g_gx  [SB*G3];               // [s][b][3H]
__device__ float g_gi  [BT*G3];               // [t][b][3H]
__device__ float g_p   [BATCH*G3];            // ctx @ Wp^T + bp
__device__ float g_h   [2][BATCH*HID];        // encoder hidden ping-pong
__device__ float g_dh  [2][BATCH*HID];        // decoder hidden ping-pong
__device__ float g_trgh[BT*HID];              // decoder outputs, row = b*T+t
__device__ __nv_bfloat16 g_hb[BT*HID];        // bf16 copy of trg_h
__device__ __nv_bfloat16 g_Wb[VOC*HID];       // bf16 copy of out_W
__device__ float g_logits[(size_t)BT*VOC];    // 262 MB
__device__ float g_rownll[BT];

// ---------------- helpers ---------------------------------------------------
__device__ __forceinline__ float sigf(float x) { return 1.0f / (1.0f + __expf(-x)); }

// ---------------- weight transpose ------------------------------------------
// W: [G3][HID] -> WT: [HID][G3].  which: 0 -> g_WhhT, 1 -> g_WhT
__global__ void k_transpose(const float* __restrict__ W, int which) {
    int i = blockIdx.x * 256 + threadIdx.x;
    if (i >= G3 * HID) return;
    int r = i / HID, k = i % HID;
    float* WT = which ? g_WhT : g_WhhT;
    WT[k * G3 + r] = W[i];
}

__global__ void k_zero_h0() {
    int i = blockIdx.x * 256 + threadIdx.x;
    if (i < BATCH * HID) g_h[0][i] = 0.0f;
}

__global__ void k_init_dec() {
    int i = blockIdx.x * 256 + threadIdx.x;
    if (i < BATCH * HID) g_dh[0][i] = g_h[0][i];   // encoder final state (parity 0)
}

// ---------------- generic input GEMM:  out[m][n] = A_row(m) . W[n][:] + bias[n]
// A_row: gathered embedding (ids != null, ids layout [B][ids_len], m = seq*B + b)
//        or direct matrix (a_from_ctx: A = g_h[0], else Asrc), K columns.
// out (N = G3): outsel 0 -> g_gx, 1 -> g_gi, 2 -> g_p
__global__ void k_big_gemm(const float* __restrict__ Asrc,
                           const int* __restrict__ ids, int ids_len,
                           int rows, int K,
                           const float* __restrict__ W,
                           const float* __restrict__ bias,
                           int outsel, int a_from_ctx) {
    __shared__ float As[64][17];
    __shared__ float Bs[16][65];
    __shared__ int   sIds[64];

    float* out = (outsel == 0) ? g_gx : (outsel == 1) ? g_gi : g_p;
    const float* Abase = a_from_ctx ? g_h[0] : Asrc;

    int tid = threadIdx.x;                // 256 threads
    int m0 = blockIdx.y * 64, n0 = blockIdx.x * 64;
    int ty = tid / 16, tx = tid % 16;

    if (ids) {
        for (int i = tid; i < 64; i += 256) {
            int m = m0 + i;
            sIds[i] = (m < rows) ? ids[(m % BATCH) * ids_len + (m / BATCH)] : 0;
        }
        __syncthreads();
    }

    float acc[4][4];
#pragma unroll
    for (int i = 0; i < 4; i++)
#pragma unroll
        for (int j = 0; j < 4; j++) acc[i][j] = 0.0f;

    for (int k0 = 0; k0 < K; k0 += 16) {
        for (int i = tid; i < 1024; i += 256) {
            int r = i / 16, kk = i % 16;
            int m = m0 + r;
            float v = 0.0f;
            if (m < rows) {
                const float* ap = ids ? (Abase + (size_t)sIds[r] * K)
                                      : (Abase + (size_t)m * K);
                v = ap[k0 + kk];
            }
            As[r][kk] = v;
        }
        for (int i = tid; i < 1024; i += 256) {
            int n = i / 16, kk = i % 16;
            Bs[kk][n] = W[(size_t)(n0 + n) * K + k0 + kk];
        }
        __syncthreads();
#pragma unroll
        for (int kk = 0; kk < 16; kk++) {
            float a[4], b[4];
#pragma unroll
            for (int i = 0; i < 4; i++) a[i] = As[ty * 4 + i][kk];
#pragma unroll
            for (int j = 0; j < 4; j++) b[j] = Bs[kk][tx * 4 + j];
#pragma unroll
            for (int i = 0; i < 4; i++)
#pragma unroll
                for (int j = 0; j < 4; j++) acc[i][j] += a[i] * b[j];
        }
        __syncthreads();
    }

#pragma unroll
    for (int i = 0; i < 4; i++) {
        int m = m0 + ty * 4 + i;
        if (m >= rows) continue;
#pragma unroll
        for (int j = 0; j < 4; j++) {
            int n = n0 + tx * 4 + j;
            out[(size_t)m * G3 + n] = acc[i][j] + bias[n];
        }
    }
}

// ---------------- encoder GRU step ------------------------------------------
// grid (16 j-chunks of 32, 8 batch-groups of 4), block 96 (3 warps, one per gate)
__global__ void k_enc_step(const float* __restrict__ bhh,
                           const int* __restrict__ src_len, int s) {
    __shared__ float hs[4][HID];
    __shared__ float sgh[3][4][32];

    const float* hprev = g_h[s & 1];
    float* hnext = g_h[(s + 1) & 1];
    const float* gx_s = g_gx + (size_t)s * BATCH * G3;

    int t = threadIdx.x;
    int bg = blockIdx.y * 4;
    int jbase = blockIdx.x * 32;

    for (int i = t; i < 4 * HID; i += 96)
        ((float*)hs)[i] = hprev[bg * HID + i];
    __syncthreads();

    int g = t / 32, jl = t % 32;
    int col = g * HID + jbase + jl;
    float a0 = 0, a1 = 0, a2 = 0, a3 = 0;
    const float* wp = g_WhhT + col;
#pragma unroll 8
    for (int k = 0; k < HID; k++) {
        float w = wp[k * G3];
        a0 += hs[0][k] * w; a1 += hs[1][k] * w;
        a2 += hs[2][k] * w; a3 += hs[3][k] * w;
    }
    float bb = bhh[col];
    sgh[g][0][jl] = a0 + bb; sgh[g][1][jl] = a1 + bb;
    sgh[g][2][jl] = a2 + bb; sgh[g][3][jl] = a3 + bb;
    __syncthreads();

    for (int idx = t; idx < 128; idx += 96) {
        int b = idx / 32, jl2 = idx % 32;
        int bbg = bg + b, j = jbase + jl2;
        const float* gxr = gx_s + (size_t)bbg * G3;
        float r = sigf(gxr[j]           + sgh[0][b][jl2]);
        float z = sigf(gxr[HID + j]     + sgh[1][b][jl2]);
        float n = tanhf(gxr[2 * HID + j] + r * sgh[2][b][jl2]);
        float hold = hs[b][j];
        float hnew = (1.0f - z) * n + z * hold;
        hnext[bbg * HID + j] = (s < src_len[bbg]) ? hnew : hold;
    }
}

// ---------------- decoder (conditional GRU) step ----------------------------
__global__ void k_dec_step(const float* __restrict__ bh, int tstep) {
    __shared__ float hs[4][HID];
    __shared__ float sgh[3][4][32];

    const float* hprev = g_dh[tstep & 1];
    float* hnext = g_dh[(tstep + 1) & 1];
    const float* gi_t = g_gi + (size_t)tstep * BATCH * G3;

    int t = threadIdx.x;
    int bg = blockIdx.y * 4;
    int jbase = blockIdx.x * 32;

    for (int i = t; i < 4 * HID; i += 96)
        ((float*)hs)[i] = hprev[bg * HID + i];
    __syncthreads();

    int g = t / 32, jl = t % 32;
    int col = g * HID + jbase + jl;
    float a0 = 0, a1 = 0, a2 = 0, a3 = 0;
    const float* wp = g_WhT + col;
#pragma unroll 8
    for (int k = 0; k < HID; k++) {
        float w = wp[k * G3];
        a0 += hs[0][k] * w; a1 += hs[1][k] * w;
        a2 += hs[2][k] * w; a3 += hs[3][k] * w;
    }
    float bb = bh[col];
    sgh[g][0][jl] = a0 + bb; sgh[g][1][jl] = a1 + bb;
    sgh[g][2][jl] = a2 + bb; sgh[g][3][jl] = a3 + bb;
    __syncthreads();

    for (int idx = t; idx < 128; idx += 96) {
        int b = idx / 32, jl2 = idx % 32;
        int bbg = bg + b, j = jbase + jl2;
        const float* gir = gi_t + (size_t)bbg * G3;
        const float* pr  = g_p + (size_t)bbg * G3;
        float r  = sigf(gir[j]           + sgh[0][b][jl2] + pr[j]);
        float ig = sigf(gir[HID + j]     + sgh[1][b][jl2] + pr[HID + j]);
        float n  = tanhf(gir[2 * HID + j] + r * sgh[2][b][jl2] + pr[2 * HID + j]);
        float hold = hs[b][j];
        float hy = n + ig * (hold - n);
        hnext[bbg * HID + j] = hy;
        g_trgh[(size_t)(bbg * TLEN + tstep) * HID + j] = hy;
    }
}

// ---------------- fp32 -> bf16 conversions ----------------------------------
__global__ void k_conv_h() {
    int i = blockIdx.x * 256 + threadIdx.x;
    if (i < BT * HID) g_hb[i] = __float2bfloat16(g_trgh[i]);
}
__global__ void k_conv_w(const float* __restrict__ w) {
    int i = blockIdx.x * 256 + threadIdx.x;
    if (i < VOC * HID) g_Wb[i] = __float2bfloat16(w[i]);
}

// ---------------- output projection: bf16 mma.sync GEMM ---------------------
// C[2048][32000] = A[2048][512] * W[32000][512]^T + bias
// block 256 thr (8 warps 2x4), block tile 64(M) x 128(N), warp tile 32x32.
__global__ void k_out_gemm(const float* __restrict__ bias) {
    int lane = threadIdx.x & 31, warp = threadIdx.x >> 5;
    int wm = warp >> 2, wn = warp & 3;
    int m_base = blockIdx.y * 64 + wm * 32;
    int n_base = blockIdx.x * 128 + wn * 32;
    int gid = lane >> 2, tg = lane & 3;

    float c[2][4][4];
#pragma unroll
    for (int mt = 0; mt < 2; mt++)
#pragma unroll
        for (int nt = 0; nt < 4; nt++)
#pragma unroll
            for (int q = 0; q < 4; q++) c[mt][nt][q] = 0.0f;

    for (int k0 = 0; k0 < HID; k0 += 16) {
        uint32_t a[2][4];
#pragma unroll
        for (int mt = 0; mt < 2; mt++) {
            const __nv_bfloat16* ap =
                g_hb + (size_t)(m_base + mt * 16 + gid) * HID + k0 + tg * 2;
            a[mt][0] = *(const uint32_t*)(ap);
            a[mt][1] = *(const uint32_t*)(ap + 8 * HID);
            a[mt][2] = *(const uint32_t*)(ap + 8);
            a[mt][3] = *(const uint32_t*)(ap + 8 * HID + 8);
        }
#pragma unroll
        for (int nt = 0; nt < 4; nt++) {
            const __nv_bfloat16* bp =
                g_Wb + (size_t)(n_base + nt * 8 + gid) * HID + k0 + tg * 2;
            uint32_t b0 = *(const uint32_t*)(bp);
            uint32_t b1 = *(const uint32_t*)(bp + 8);
#pragma unroll
            for (int mt = 0; mt < 2; mt++) {
                asm volatile(
                    "mma.sync.aligned.m16n8k16.row.col.f32.bf16.bf16.f32 "
                    "{%0,%1,%2,%3}, {%4,%5,%6,%7}, {%8,%9}, {%0,%1,%2,%3};"
                    : "+f"(c[mt][nt][0]), "+f"(c[mt][nt][1]),
                      "+f"(c[mt][nt][2]), "+f"(c[mt][nt][3])
                    : "r"(a[mt][0]), "r"(a[mt][1]), "r"(a[mt][2]), "r"(a[mt][3]),
                      "r"(b0), "r"(b1));
            }
        }
    }

#pragma unroll
    for (int mt = 0; mt < 2; mt++)
#pragma unroll
        for (int nt = 0; nt < 4; nt++) {
            int row = m_base + mt * 16 + gid;
            int col = n_base + nt * 8 + tg * 2;
            float bv0 = bias[col], bv1 = bias[col + 1];
            g_logits[(size_t)row * VOC + col]           = c[mt][nt][0] + bv0;
            g_logits[(size_t)row * VOC + col + 1]       = c[mt][nt][1] + bv1;
            g_logits[(size_t)(row + 8) * VOC + col]     = c[mt][nt][2] + bv0;
            g_logits[(size_t)(row + 8) * VOC + col + 1] = c[mt][nt][3] + bv1;
        }
}

// ---------------- per-row logsumexp + NLL -----------------------------------
__global__ void k_nll(const int* __restrict__ trg_out) {
    int r = blockIdx.x;                    // 0..2047, r = b*T + t
    const float* row = g_logits + (size_t)r * VOC;
    __shared__ float red[256];
    int t = threadIdx.x;

    float m = -1e30f;
    for (int v = t; v < VOC; v += 256) m = fmaxf(m, row[v]);
    red[t] = m; __syncthreads();
    for (int s = 128; s > 0; s >>= 1) {
        if (t < s) red[t] = fmaxf(red[t], red[t + s]);
        __syncthreads();
    }
    float rowmax = red[0]; __syncthreads();

    float ssum = 0.0f;
    for (int v = t; v < VOC; v += 256) ssum += __expf(row[v] - rowmax);
    red[t] = ssum; __syncthreads();
    for (int s = 128; s > 0; s >>= 1) {
        if (t < s) red[t] += red[t + s];
        __syncthreads();
    }
    if (t == 0) {
        int target = trg_out[r];
        g_rownll[r] = rowmax + logf(red[0]) - row[target];
    }
}

__global__ void k_mean(float* __restrict__ out) {
    __shared__ float red[256];
    int t = threadIdx.x;
    float s = 0.0f;
    for (int i = t; i < BT; i += 256) s += g_rownll[i];
    red[t] = s; __syncthreads();
    for (int k = 128; k > 0; k >>= 1) {
        if (t < k) red[t] += red[t + k];
        __syncthreads();
    }
    if (t == 0) out[0] = red[0] / (float)BT;
}

// ---------------- launch -----------------------------------------------------
extern "C" void kernel_launch(void* const* d_in, const int* in_sizes, int n_in,
                              void* d_out, int out_size) {
    const int*   src      = (const int*)  d_in[0];
    const int*   src_len  = (const int*)  d_in[1];
    const int*   trg_in   = (const int*)  d_in[2];
    const int*   trg_out  = (const int*)  d_in[3];
    const float* src_emb  = (const float*)d_in[4];
    const float* trg_emb  = (const float*)d_in[5];
    const float* enc_Wih  = (const float*)d_in[6];
    const float* enc_Whh  = (const float*)d_in[7];
    const float* enc_bih  = (const float*)d_in[8];
    const float* enc_bhh  = (const float*)d_in[9];
    const float* dec_Wi   = (const float*)d_in[10];
    const float* dec_bi   = (const float*)d_in[11];
    const float* dec_Wh   = (const float*)d_in[12];
    const float* dec_bh   = (const float*)d_in[13];
    const float* dec_Wp   = (const float*)d_in[14];
    const float* dec_bp   = (const float*)d_in[15];
    const float* out_W    = (const float*)d_in[16];
    const float* out_b    = (const float*)d_in[17];
    float* out = (float*)d_out;

    // weight transposes + state init
    int nTr = (G3 * HID + 255) / 256;
    k_transpose<<<nTr, 256>>>(enc_Whh, 0);
    k_transpose<<<nTr, 256>>>(dec_Wh, 1);
    k_zero_h0<<<(BATCH * HID + 255) / 256, 256>>>();

    // encoder input GEMM: gx = emb(src) @ Wih^T + bih   [4096 x 1536]
    k_big_gemm<<<dim3(G3 / 64, SB / 64), 256>>>(src_emb, src, SLEN, SB, EMB,
                                                enc_Wih, enc_bih, 0, 0);
    // decoder input GEMM: gi = emb(trg) @ Wi^T + bi     [2048 x 1536]
    k_big_gemm<<<dim3(G3 / 64, BT / 64), 256>>>(trg_emb, trg_in, TLEN, BT, EMB,
                                                dec_Wi, dec_bi, 1, 0);

    // encoder recurrence
    for (int s = 0; s < SLEN; s++)
        k_enc_step<<<dim3(16, 8), 96>>>(enc_bhh, src_len, s);

    // ctx = g_h[0]; p = ctx @ Wp^T + bp  [32 x 1536]
    k_big_gemm<<<dim3(G3 / 64, 1), 256>>>(nullptr, nullptr, 0, BATCH, HID,
                                          dec_Wp, dec_bp, 2, 1);
    k_init_dec<<<(BATCH * HID + 255) / 256, 256>>>();

    // decoder recurrence
    for (int t = 0; t < TLEN; t++)
        k_dec_step<<<dim3(16, 8), 96>>>(dec_bh, t);

    // output projection (bf16 tensor cores) + NLL
    k_conv_h<<<(BT * HID + 255) / 256, 256>>>();
    k_conv_w<<<(VOC * HID + 255) / 256, 256>>>(out_W);
    k_out_gemm<<<dim3(VOC / 128, BT / 64), 256>>>(out_b);
    k_nll<<<BT, 256>>>(trg_out);
    k_mean<<<1, 256>>>(out);
}

// round 4
// speedup vs baseline: 2.2317x; 2.2317x over previous
#include <cuda_runtime.h>
#include <cuda_bf16.h>
#include <cstdint>

#define BATCH 32
#define SLEN  128
#define TLEN  64
#define VOC   32000
#define EMB   256
#define HID   512
#define G3    1536            // 3*HID
#define BT    (BATCH*TLEN)    // 2048 decoder rows
#define SB    (SLEN*BATCH)    // 4096 encoder rows
#define RNBLK 128             // persistent recurrence blocks (<=148 SMs: co-resident)

// ---------------- scratch (device globals; no allocation allowed) ----------
__device__ float g_gx  [SB*G3];               // [s][b][3H]
__device__ float g_gi  [BT*G3];               // [t][b][3H]
__device__ float g_p   [BATCH*G3];            // ctx @ Wp^T + bp
__device__ float g_h   [2][BATCH*HID];        // hidden ping-pong (enc then dec)
__device__ __nv_bfloat16 g_hb[BT*HID];        // bf16 decoder outputs, row = b*T+t
__device__ __nv_bfloat16 g_Wb[VOC*HID];       // bf16 copy of out_W
__device__ float g_logits[(size_t)BT*VOC];    // 262 MB
__device__ float g_rownll[BT];
__device__ unsigned g_barE, g_barD;

__device__ __forceinline__ float sigf(float x) { return 1.0f / (1.0f + __expf(-x)); }

__global__ void k_reset_bars() { g_barE = 0; g_barD = 0; }

__global__ void k_zero_h0() {
    int i = blockIdx.x * 256 + threadIdx.x;
    if (i < BATCH * HID) g_h[0][i] = 0.0f;
}

// ---------------- input GEMM:  out[m][n] = A_row(m) . W[n][:] + bias[n] -----
// ids != null: gathered embedding, m = seq*B + b ; else A = g_h[0] (ctx).
__global__ void k_big_gemm(const float* __restrict__ Asrc,
                           const int* __restrict__ ids, int ids_len,
                           int rows, int K,
                           const float* __restrict__ W,
                           const float* __restrict__ bias,
                           int outsel, int a_from_ctx) {
    __shared__ __align__(16) float As[16][72];   // [kk][m]
    __shared__ __align__(16) float Bs[16][72];   // [kk][n]
    __shared__ int sIds[64];

    float* out = (outsel == 0) ? g_gx : (outsel == 1) ? g_gi : g_p;
    const float* Abase = a_from_ctx ? g_h[0] : Asrc;

    int tid = threadIdx.x;                // 256 threads
    int m0 = blockIdx.y * 64, n0 = blockIdx.x * 64;
    int ty = tid / 16, tx = tid % 16;

    if (ids) {
        for (int i = tid; i < 64; i += 256) {
            int m = m0 + i;
            sIds[i] = (m < rows) ? ids[(m % BATCH) * ids_len + (m / BATCH)] : 0;
        }
        __syncthreads();
    }

    float acc[4][4];
#pragma unroll
    for (int i = 0; i < 4; i++)
#pragma unroll
        for (int j = 0; j < 4; j++) acc[i][j] = 0.0f;

    for (int k0 = 0; k0 < K; k0 += 16) {
        for (int i = tid; i < 1024; i += 256) {
            int r = i / 16, kk = i % 16;
            int m = m0 + r;
            float v = 0.0f;
            if (m < rows) {
                const float* ap = ids ? (Abase + (size_t)sIds[r] * K)
                                      : (Abase + (size_t)m * K);
                v = ap[k0 + kk];
            }
            As[kk][r] = v;
        }
        for (int i = tid; i < 1024; i += 256) {
            int n = i / 16, kk = i % 16;
            Bs[kk][n] = W[(size_t)(n0 + n) * K + k0 + kk];
        }
        __syncthreads();
#pragma unroll
        for (int kk = 0; kk < 16; kk++) {
            float4 a4 = *(const float4*)&As[kk][ty * 4];
            float4 b4 = *(const float4*)&Bs[kk][tx * 4];
            float a[4] = {a4.x, a4.y, a4.z, a4.w};
            float b[4] = {b4.x, b4.y, b4.z, b4.w};
#pragma unroll
            for (int i = 0; i < 4; i++)
#pragma unroll
                for (int j = 0; j < 4; j++) acc[i][j] += a[i] * b[j];
        }
        __syncthreads();
    }

#pragma unroll
    for (int i = 0; i < 4; i++) {
        int m = m0 + ty * 4 + i;
        if (m >= rows) continue;
#pragma unroll
        for (int j = 0; j < 4; j++) {
            int n = n0 + tx * 4 + j;
            out[(size_t)m * G3 + n] = acc[i][j] + bias[n];
        }
    }
}

// ---------------- persistent recurrence -------------------------------------
// 128 blocks x 384 threads. Block owns 4 h-cols (12 gate cols, all batches).
// Weight slice cached in smem for the whole sequence; one grid barrier/step.
template<int STEPS, bool DEC>
__global__ void __launch_bounds__(384, 1)
k_recur(const float* __restrict__ Wrec,   // [G3][HID] row-major
        const float* __restrict__ brec,   // [G3]
        const int* __restrict__ src_len)  // encoder only
{
    extern __shared__ float sm[];
    float* Wsm = sm;                      // 12*512
    float* hsm = sm + 12 * 512;           // 32*516 (padded rows)
    float* ghm = hsm + 32 * 516;          // 12*32
    float* psm = ghm + 12 * 32;           // 12*32 (dec)

    const int t = threadIdx.x;            // 384
    const int j0 = blockIdx.x * 4;

    for (int i = t; i < 12 * 512; i += 384) {
        int c = i >> 9, k = i & 511;
        int row = (c >> 2) * 512 + j0 + (c & 3);
        Wsm[i] = Wrec[row * 512 + k];
    }
    if (DEC) {
        int c = t >> 5, b = t & 31;       // 384 threads -> 12x32 exactly
        psm[t] = g_p[b * G3 + (c >> 2) * 512 + j0 + (c & 3)];
    }
    const int wc = t >> 5;                // warp -> gate-col 0..11
    const int lb = t & 31;                // lane -> batch
    const float bcol = brec[(wc >> 2) * 512 + j0 + (wc & 3)];
    __syncthreads();

    unsigned* bar = DEC ? &g_barD : &g_barE;

    for (int s = 0; s < STEPS; s++) {
        const float* hprev = g_h[s & 1];
        float* hnext = g_h[(s + 1) & 1];

        // stage h[32][512] to smem (L2-coherent reads)
        for (int f = t; f < 4096; f += 384) {
            int b = f >> 7, kq = f & 127;
            float4 v = __ldcg((const float4*)(hprev + b * 512 + kq * 4));
            *(float4*)(hsm + b * 516 + kq * 4) = v;
        }
        __syncthreads();

        // dot: gh[c][b] = h[b][:] . W[c][:] + b[c]
        {
            const float* wp = Wsm + wc * 512;
            const float* hp = hsm + lb * 516;
            float a0 = 0.f, a1 = 0.f, a2 = 0.f, a3 = 0.f;
#pragma unroll 8
            for (int k = 0; k < 512; k += 4) {
                float4 w = *(const float4*)(wp + k);
                float4 h = *(const float4*)(hp + k);
                a0 += w.x * h.x; a1 += w.y * h.y;
                a2 += w.z * h.z; a3 += w.w * h.w;
            }
            ghm[wc * 32 + lb] = (a0 + a1) + (a2 + a3) + bcol;
        }
        __syncthreads();

        // combine gates + write new h (threads 0..127)
        if (t < 128) {
            int b = t & 31, hc = t >> 5;
            int j = j0 + hc;
            const float* gr = (DEC ? g_gi : g_gx) + ((size_t)s * BATCH + b) * G3;
            float ghr = ghm[hc * 32 + b];
            float ghz = ghm[(4 + hc) * 32 + b];
            float ghn = ghm[(8 + hc) * 32 + b];
            float hold = hsm[b * 516 + j];
            float hy;
            if (DEC) {
                float r  = sigf(gr[j]          + ghr + psm[hc * 32 + b]);
                float ig = sigf(gr[512 + j]    + ghz + psm[(4 + hc) * 32 + b]);
                float nn = tanhf(gr[1024 + j]  + r * ghn + psm[(8 + hc) * 32 + b]);
                hy = nn + ig * (hold - nn);
                g_hb[((size_t)b * TLEN + s) * HID + j] = __float2bfloat16(hy);
            } else {
                float r  = sigf(gr[j] + ghr);
                float z  = sigf(gr[512 + j] + ghz);
                float nn = tanhf(gr[1024 + j] + r * ghn);
                float hn = (1.0f - z) * nn + z * hold;
                hy = (s < src_len[b]) ? hn : hold;
            }
            __stcg(hnext + b * 512 + j, hy);
        }

        if (s + 1 < STEPS) {               // grid barrier
            __threadfence();
            __syncthreads();
            if (t == 0) {
                atomicAdd(bar, 1u);
                unsigned target = (unsigned)(s + 1) * RNBLK;
                while (*(volatile unsigned*)bar < target) __nanosleep(32);
            }
            __syncthreads();
        }
    }
}

// ---------------- fp32 -> bf16 weight conversion -----------------------------
__global__ void k_conv_w(const float* __restrict__ w) {
    int i = blockIdx.x * 256 + threadIdx.x;   // over VOC*HID/2 pairs
    if (i < VOC * HID / 2) {
        float2 a = ((const float2*)w)[i];
        ((__nv_bfloat162*)g_Wb)[i] = __floats2bfloat162_rn(a.x, a.y);
    }
}

// ---------------- output projection: bf16 mma.sync GEMM ---------------------
// C[2048][32000] = A[2048][512] * W[32000][512]^T + bias
// block 256 thr (8 warps 4x2), tile M=128 x N=64, warp tile 32x32.
__global__ void k_out_gemm(const float* __restrict__ bias) {
    int lane = threadIdx.x & 31, warp = threadIdx.x >> 5;
    int wm = warp >> 1, wn = warp & 1;
    int m_base = blockIdx.y * 128 + wm * 32;
    int n_base = blockIdx.x * 64 + wn * 32;
    int gid = lane >> 2, tg = lane & 3;

    float c[2][4][4];
#pragma unroll
    for (int mt = 0; mt < 2; mt++)
#pragma unroll
        for (int nt = 0; nt < 4; nt++)
#pragma unroll
            for (int q = 0; q < 4; q++) c[mt][nt][q] = 0.0f;

    for (int k0 = 0; k0 < HID; k0 += 16) {
        uint32_t a[2][4];
#pragma unroll
        for (int mt = 0; mt < 2; mt++) {
            const __nv_bfloat16* ap =
                g_hb + (size_t)(m_base + mt * 16 + gid) * HID + k0 + tg * 2;
            a[mt][0] = *(const uint32_t*)(ap);
            a[mt][1] = *(const uint32_t*)(ap + 8 * HID);
            a[mt][2] = *(const uint32_t*)(ap + 8);
            a[mt][3] = *(const uint32_t*)(ap + 8 * HID + 8);
        }
#pragma unroll
        for (int nt = 0; nt < 4; nt++) {
            const __nv_bfloat16* bp =
                g_Wb + (size_t)(n_base + nt * 8 + gid) * HID + k0 + tg * 2;
            uint32_t b0 = *(const uint32_t*)(bp);
            uint32_t b1 = *(const uint32_t*)(bp + 8);
#pragma unroll
            for (int mt = 0; mt < 2; mt++) {
                asm volatile(
                    "mma.sync.aligned.m16n8k16.row.col.f32.bf16.bf16.f32 "
                    "{%0,%1,%2,%3}, {%4,%5,%6,%7}, {%8,%9}, {%0,%1,%2,%3};"
                    : "+f"(c[mt][nt][0]), "+f"(c[mt][nt][1]),
                      "+f"(c[mt][nt][2]), "+f"(c[mt][nt][3])
                    : "r"(a[mt][0]), "r"(a[mt][1]), "r"(a[mt][2]), "r"(a[mt][3]),
                      "r"(b0), "r"(b1));
            }
        }
    }

#pragma unroll
    for (int mt = 0; mt < 2; mt++)
#pragma unroll
        for (int nt = 0; nt < 4; nt++) {
            int row = m_base + mt * 16 + gid;
            int col = n_base + nt * 8 + tg * 2;
            float bv0 = bias[col], bv1 = bias[col + 1];
            g_logits[(size_t)row * VOC + col]           = c[mt][nt][0] + bv0;
            g_logits[(size_t)row * VOC + col + 1]       = c[mt][nt][1] + bv1;
            g_logits[(size_t)(row + 8) * VOC + col]     = c[mt][nt][2] + bv0;
            g_logits[(size_t)(row + 8) * VOC + col + 1] = c[mt][nt][3] + bv1;
        }
}

// ---------------- single-pass online logsumexp + NLL ------------------------
__global__ void k_nll(const int* __restrict__ trg_out) {
    int r = blockIdx.x;                    // 0..2047, r = b*T + t
    const float* row = g_logits + (size_t)r * VOC;
    const float4* row4 = (const float4*)row;
    int t = threadIdx.x;

    float m = -1e30f, sum = 0.0f;
    for (int v = t; v < VOC / 4; v += 256) {
        float4 x4 = row4[v];
        float xs[4] = {x4.x, x4.y, x4.z, x4.w};
#pragma unroll
        for (int q = 0; q < 4; q++) {
            float xv = xs[q];
            if (xv > m) { sum = sum * __expf(m - xv) + 1.0f; m = xv; }
            else sum += __expf(xv - m);
        }
    }
    __shared__ float sm_[256], ss_[256];
    sm_[t] = m; ss_[t] = sum; __syncthreads();
    for (int k = 128; k > 0; k >>= 1) {
        if (t < k) {
            float m2 = sm_[t + k], s2 = ss_[t + k];
            float M = fmaxf(sm_[t], m2);
            ss_[t] = ss_[t] * __expf(sm_[t] - M) + s2 * __expf(m2 - M);
            sm_[t] = M;
        }
        __syncthreads();
    }
    if (t == 0) g_rownll[r] = sm_[0] + logf(ss_[0]) - row[trg_out[r]];
}

__global__ void k_mean(float* __restrict__ out) {
    __shared__ float red[256];
    int t = threadIdx.x;
    float s = 0.0f;
    for (int i = t; i < BT; i += 256) s += g_rownll[i];
    red[t] = s; __syncthreads();
    for (int k = 128; k > 0; k >>= 1) {
        if (t < k) red[t] += red[t + k];
        __syncthreads();
    }
    if (t == 0) out[0] = red[0] / (float)BT;
}

// ---------------- launch -----------------------------------------------------
extern "C" void kernel_launch(void* const* d_in, const int* in_sizes, int n_in,
                              void* d_out, int out_size) {
    const int*   src      = (const int*)  d_in[0];
    const int*   src_len  = (const int*)  d_in[1];
    const int*   trg_in   = (const int*)  d_in[2];
    const int*   trg_out  = (const int*)  d_in[3];
    const float* src_emb  = (const float*)d_in[4];
    const float* trg_emb  = (const float*)d_in[5];
    const float* enc_Wih  = (const float*)d_in[6];
    const float* enc_Whh  = (const float*)d_in[7];
    const float* enc_bih  = (const float*)d_in[8];
    const float* enc_bhh  = (const float*)d_in[9];
    const float* dec_Wi   = (const float*)d_in[10];
    const float* dec_bi   = (const float*)d_in[11];
    const float* dec_Wh   = (const float*)d_in[12];
    const float* dec_bh   = (const float*)d_in[13];
    const float* dec_Wp   = (const float*)d_in[14];
    const float* dec_bp   = (const float*)d_in[15];
    const float* out_W    = (const float*)d_in[16];
    const float* out_b    = (const float*)d_in[17];
    float* out = (float*)d_out;

    const int SMEMB = (12 * 512 + 32 * 516 + 12 * 32 + 12 * 32) * 4;  // 93696
    cudaFuncSetAttribute(k_recur<SLEN, false>,
                         cudaFuncAttributeMaxDynamicSharedMemorySize, SMEMB);
    cudaFuncSetAttribute(k_recur<TLEN, true>,
                         cudaFuncAttributeMaxDynamicSharedMemorySize, SMEMB);

    k_reset_bars<<<1, 1>>>();
    k_zero_h0<<<(BATCH * HID + 255) / 256, 256>>>();

    // gx = emb(src) @ Wih^T + bih   [4096 x 1536]
    k_big_gemm<<<dim3(G3 / 64, SB / 64), 256>>>(src_emb, src, SLEN, SB, EMB,
                                                enc_Wih, enc_bih, 0, 0);
    // gi = emb(trg) @ Wi^T + bi     [2048 x 1536]
    k_big_gemm<<<dim3(G3 / 64, BT / 64), 256>>>(trg_emb, trg_in, TLEN, BT, EMB,
                                                dec_Wi, dec_bi, 1, 0);
    // bf16 weights for output projection (independent; overlaps nothing anyway)
    k_conv_w<<<(VOC * HID / 2 + 255) / 256, 256>>>(out_W);

    // encoder: all 128 steps in one persistent kernel
    k_recur<SLEN, false><<<RNBLK, 384, SMEMB>>>(enc_Whh, enc_bhh, src_len);

    // p = ctx @ Wp^T + bp  (ctx = final encoder h in g_h[0])
    k_big_gemm<<<dim3(G3 / 64, 1), 256>>>(nullptr, nullptr, 0, BATCH, HID,
                                          dec_Wp, dec_bp, 2, 1);

    // decoder: all 64 steps in one persistent kernel (writes g_hb bf16)
    k_recur<TLEN, true><<<RNBLK, 384, SMEMB>>>(dec_Wh, dec_bh, nullptr);

    // output projection + NLL
    k_out_gemm<<<dim3(VOC / 64, BT / 128), 256>>>(out_b);
    k_nll<<<BT, 256>>>(trg_out);
    k_mean<<<1, 256>>>(out);
}

// round 5
// speedup vs baseline: 2.7328x; 1.2246x over previous
#include <cuda_runtime.h>
#include <cuda_bf16.h>
#include <cstdint>

#define BATCH 32
#define SLEN  128
#define TLEN  64
#define VOC   32000
#define EMB   256
#define HID   512
#define G3    1536            // 3*HID
#define BT    (BATCH*TLEN)    // 2048 decoder rows
#define SB    (SLEN*BATCH)    // 4096 encoder rows
#define RNBLK 128             // persistent recurrence blocks (<=148 SMs)
#define NBLKS (VOC/64)        // 500 n-blocks in output projection

// ---------------- scratch (device globals; no allocation allowed) ----------
__device__ float g_gx  [SB*G3];               // [s][b][3H]
__device__ float g_gi  [BT*G3];               // [t][b][3H]
__device__ float g_p   [BATCH*G3];            // ctx @ Wp^T + bp
__device__ float g_h   [2][BATCH*HID];        // hidden ping-pong (enc then dec)
__device__ __nv_bfloat16 g_hb[BT*HID];        // bf16 decoder outputs, row = b*T+t
__device__ __nv_bfloat16 g_Wb[VOC*HID];       // bf16 copy of out_W
__device__ float2 g_part[(size_t)BT*NBLKS];   // per (row, nblk) {max, sumexp}
__device__ float g_tgt[BT];                   // target logit per row (with bias)
__device__ float g_rownll[BT];
__device__ unsigned g_barE, g_barD;

__device__ __forceinline__ float sigf(float x) { return 1.0f / (1.0f + __expf(-x)); }

__global__ void k_reset_bars() { g_barE = 0; g_barD = 0; }

__global__ void k_zero_h0() {
    int i = blockIdx.x * 256 + threadIdx.x;
    if (i < BATCH * HID) g_h[0][i] = 0.0f;
}

// ---------------- input GEMM:  out[m][n] = A_row(m) . W[n][:] + bias[n] -----
__global__ void k_big_gemm(const float* __restrict__ Asrc,
                           const int* __restrict__ ids, int ids_len,
                           int rows, int K,
                           const float* __restrict__ W,
                           const float* __restrict__ bias,
                           int outsel, int a_from_ctx) {
    __shared__ __align__(16) float As[16][72];   // [kk][m]
    __shared__ __align__(16) float Bs[16][72];   // [kk][n]
    __shared__ int sIds[64];

    float* out = (outsel == 0) ? g_gx : (outsel == 1) ? g_gi : g_p;
    const float* Abase = a_from_ctx ? g_h[0] : Asrc;

    int tid = threadIdx.x;                // 256 threads
    int m0 = blockIdx.y * 64, n0 = blockIdx.x * 64;
    int ty = tid / 16, tx = tid % 16;

    if (ids) {
        for (int i = tid; i < 64; i += 256) {
            int m = m0 + i;
            sIds[i] = (m < rows) ? ids[(m % BATCH) * ids_len + (m / BATCH)] : 0;
        }
        __syncthreads();
    }

    float acc[4][4];
#pragma unroll
    for (int i = 0; i < 4; i++)
#pragma unroll
        for (int j = 0; j < 4; j++) acc[i][j] = 0.0f;

    for (int k0 = 0; k0 < K; k0 += 16) {
        for (int i = tid; i < 1024; i += 256) {
            int r = i / 16, kk = i % 16;
            int m = m0 + r;
            float v = 0.0f;
            if (m < rows) {
                const float* ap = ids ? (Abase + (size_t)sIds[r] * K)
                                      : (Abase + (size_t)m * K);
                v = ap[k0 + kk];
            }
            As[kk][r] = v;
        }
        for (int i = tid; i < 1024; i += 256) {
            int n = i / 16, kk = i % 16;
            Bs[kk][n] = W[(size_t)(n0 + n) * K + k0 + kk];
        }
        __syncthreads();
#pragma unroll
        for (int kk = 0; kk < 16; kk++) {
            float4 a4 = *(const float4*)&As[kk][ty * 4];
            float4 b4 = *(const float4*)&Bs[kk][tx * 4];
            float a[4] = {a4.x, a4.y, a4.z, a4.w};
            float b[4] = {b4.x, b4.y, b4.z, b4.w};
#pragma unroll
            for (int i = 0; i < 4; i++)
#pragma unroll
                for (int j = 0; j < 4; j++) acc[i][j] += a[i] * b[j];
        }
        __syncthreads();
    }

#pragma unroll
    for (int i = 0; i < 4; i++) {
        int m = m0 + ty * 4 + i;
        if (m >= rows) continue;
#pragma unroll
        for (int j = 0; j < 4; j++) {
            int n = n0 + tx * 4 + j;
            out[(size_t)m * G3 + n] = acc[i][j] + bias[n];
        }
    }
}

// ---------------- persistent recurrence v2 ----------------------------------
// 128 blocks x 384 thr (12 warps). Block owns 4 h-cols (12 gate cols).
// Dot: warp = (col-group cw of 4 cols, k-chunk kc of 128); lane = (cl, o),
// computes 4 batch outputs (o, o+8, o+16, o+24). Partials reduced via smem.
// Grid barrier: single-thread release/acquire atomics.
template<int STEPS, bool DEC>
__global__ void __launch_bounds__(384, 1)
k_recur(const float* __restrict__ Wrec,   // [G3][HID] row-major
        const float* __restrict__ brec,   // [G3]
        const int* __restrict__ src_len)  // encoder only
{
    extern __shared__ float sm[];
    float* Wsm = sm;                       // 12*520
    float* hsm = Wsm + 12 * 520;           // 32*516
    float* red = hsm + 32 * 516;           // 4*384 partials
    float* ghm = red + 4 * 384;            // 384 reduced gates

    const int t = threadIdx.x;
    const int j0 = blockIdx.x * 4;

    // cache weight slice (12 gate rows x 512) in smem, padded to 520
    for (int i = t; i < 12 * 512; i += 384) {
        int gc = i >> 9, k = i & 511;
        Wsm[gc * 520 + k] = Wrec[(size_t)((gc >> 2) * 512 + j0 + (gc & 3)) * 512 + k];
    }

    // dot-role constants
    const int w  = t >> 5;                 // warp 0..11
    const int kc = w & 3;                  // k-chunk
    const int cw = w >> 2;                 // col-group 0..2
    const int lane = t & 31;
    const int cl = lane >> 3, o = lane & 7;
    const int gc_d = cw * 4 + cl;

    // reduce-role constants
    const int gc_r = t >> 5;               // 0..11
    const int b_r  = t & 31;
    const float biasr = brec[(gc_r >> 2) * 512 + j0 + (gc_r & 3)];

    // combine-role constants (t < 128)
    const int hc = t >> 5, bc = t & 31;    // valid when t<128
    const int jc = j0 + hc;
    float p0 = 0.f, p1 = 0.f, p2 = 0.f;
    int slen = 0;
    if (t < 128) {
        if (DEC) {
            p0 = g_p[bc * G3 + jc];
            p1 = g_p[bc * G3 + 512 + jc];
            p2 = g_p[bc * G3 + 1024 + jc];
        } else {
            slen = src_len[bc];
        }
    }
    __syncthreads();

    unsigned* bar = DEC ? &g_barD : &g_barE;
    const float* gbase = DEC ? g_gi : g_gx;

    for (int s = 0; s < STEPS; s++) {
        const float* hprev = g_h[s & 1];
        float* hnext = g_h[(s + 1) & 1];

        // prefetch this step's input-gate values (used in combine)
        float gx0 = 0.f, gx1 = 0.f, gx2 = 0.f;
        if (t < 128) {
            const float* gr = gbase + ((size_t)s * BATCH + bc) * G3;
            gx0 = gr[jc]; gx1 = gr[512 + jc]; gx2 = gr[1024 + jc];
        }

        // stage h[32][512] to smem
        for (int f = t; f < 4096; f += 384) {
            int b = f >> 7, kq = f & 127;
            float4 v = __ldcg((const float4*)(hprev + b * 512 + kq * 4));
            *(float4*)(hsm + b * 516 + kq * 4) = v;
        }
        __syncthreads();

        // dot partials: 4 batches per lane over a 128-k chunk
        {
            const float* wp = Wsm + gc_d * 520 + kc * 128;
            const float* h0 = hsm + (o     ) * 516 + kc * 128;
            const float* h1 = hsm + (o +  8) * 516 + kc * 128;
            const float* h2 = hsm + (o + 16) * 516 + kc * 128;
            const float* h3 = hsm + (o + 24) * 516 + kc * 128;
            float a0 = 0.f, a1 = 0.f, a2 = 0.f, a3 = 0.f;
#pragma unroll 8
            for (int k = 0; k < 128; k += 4) {
                float4 wv = *(const float4*)(wp + k);
                float4 v0 = *(const float4*)(h0 + k);
                float4 v1 = *(const float4*)(h1 + k);
                float4 v2 = *(const float4*)(h2 + k);
                float4 v3 = *(const float4*)(h3 + k);
                a0 += wv.x * v0.x + wv.y * v0.y + wv.z * v0.z + wv.w * v0.w;
                a1 += wv.x * v1.x + wv.y * v1.y + wv.z * v1.z + wv.w * v1.w;
                a2 += wv.x * v2.x + wv.y * v2.y + wv.z * v2.z + wv.w * v2.w;
                a3 += wv.x * v3.x + wv.y * v3.y + wv.z * v3.z + wv.w * v3.w;
            }
            float* rp = red + kc * 384 + gc_d * 32;
            rp[o] = a0; rp[o + 8] = a1; rp[o + 16] = a2; rp[o + 24] = a3;
        }
        __syncthreads();

        // reduce 4 k-chunks + bias
        ghm[gc_r * 32 + b_r] = red[gc_r * 32 + b_r] + red[384 + gc_r * 32 + b_r]
                             + red[768 + gc_r * 32 + b_r] + red[1152 + gc_r * 32 + b_r]
                             + biasr;
        __syncthreads();

        // combine gates + write new h
        if (t < 128) {
            float ghr = ghm[hc * 32 + bc];
            float ghz = ghm[(4 + hc) * 32 + bc];
            float ghn = ghm[(8 + hc) * 32 + bc];
            float hold = hsm[bc * 516 + jc];
            float hy;
            if (DEC) {
                float r  = sigf(gx0 + ghr + p0);
                float ig = sigf(gx1 + ghz + p1);
                float nn = tanhf(gx2 + r * ghn + p2);
                hy = nn + ig * (hold - nn);
                g_hb[((size_t)bc * TLEN + s) * HID + jc] = __float2bfloat16(hy);
            } else {
                float r  = sigf(gx0 + ghr);
                float z  = sigf(gx1 + ghz);
                float nn = tanhf(gx2 + r * ghn);
                float hn = (1.0f - z) * nn + z * hold;
                hy = (s < slen) ? hn : hold;
            }
            __stcg(hnext + bc * 512 + jc, hy);
        }

        // grid barrier (release/acquire, single thread)
        if (s + 1 < STEPS) {
            __syncthreads();
            if (t == 0) {
                asm volatile("red.release.gpu.global.add.u32 [%0], %1;"
                             :: "l"(bar), "r"(1u) : "memory");
                unsigned target = (unsigned)(s + 1) * RNBLK;
                unsigned v;
                do {
                    asm volatile("ld.acquire.gpu.global.u32 %0, [%1];"
                                 : "=r"(v) : "l"(bar) : "memory");
                    if (v >= target) break;
                    __nanosleep(32);
                } while (true);
            }
            __syncthreads();
        }
    }
}

// ---------------- fp32 -> bf16 weight conversion -----------------------------
__global__ void k_conv_w(const float* __restrict__ w) {
    int i = blockIdx.x * 256 + threadIdx.x;
    if (i < VOC * HID / 2) {
        float2 a = ((const float2*)w)[i];
        ((__nv_bfloat162*)g_Wb)[i] = __floats2bfloat162_rn(a.x, a.y);
    }
}

// ---------------- output projection + fused partial logsumexp ----------------
// C tile 128m x 64n per block; emits per-row {max,sumexp} partial + target logit.
__global__ void __launch_bounds__(256) k_out_gemm(const float* __restrict__ bias,
                                                  const int* __restrict__ trg_out) {
    __shared__ int   sTgt[128];
    __shared__ float sMax[2][128];
    __shared__ float sSum[2][128];

    int tid = threadIdx.x;
    int lane = tid & 31, warp = tid >> 5;
    int wm = warp >> 1, wn = warp & 1;
    int nblk = blockIdx.x, mblk = blockIdx.y;
    int rowbase = mblk * 128, n0 = nblk * 64;
    int m_base = rowbase + wm * 32;
    int n_base = n0 + wn * 32;
    int gid = lane >> 2, tg = lane & 3;

    for (int i = tid; i < 128; i += 256) sTgt[i] = trg_out[rowbase + i];
    __syncthreads();

    float c[2][4][4];
#pragma unroll
    for (int mt = 0; mt < 2; mt++)
#pragma unroll
        for (int nt = 0; nt < 4; nt++)
#pragma unroll
            for (int q = 0; q < 4; q++) c[mt][nt][q] = 0.0f;

    for (int k0 = 0; k0 < HID; k0 += 16) {
        uint32_t a[2][4];
#pragma unroll
        for (int mt = 0; mt < 2; mt++) {
            const __nv_bfloat16* ap =
                g_hb + (size_t)(m_base + mt * 16 + gid) * HID + k0 + tg * 2;
            a[mt][0] = *(const uint32_t*)(ap);
            a[mt][1] = *(const uint32_t*)(ap + 8 * HID);
            a[mt][2] = *(const uint32_t*)(ap + 8);
            a[mt][3] = *(const uint32_t*)(ap + 8 * HID + 8);
        }
#pragma unroll
        for (int nt = 0; nt < 4; nt++) {
            const __nv_bfloat16* bp =
                g_Wb + (size_t)(n_base + nt * 8 + gid) * HID + k0 + tg * 2;
            uint32_t b0 = *(const uint32_t*)(bp);
            uint32_t b1 = *(const uint32_t*)(bp + 8);
#pragma unroll
            for (int mt = 0; mt < 2; mt++) {
                asm volatile(
                    "mma.sync.aligned.m16n8k16.row.col.f32.bf16.bf16.f32 "
                    "{%0,%1,%2,%3}, {%4,%5,%6,%7}, {%8,%9}, {%0,%1,%2,%3};"
                    : "+f"(c[mt][nt][0]), "+f"(c[mt][nt][1]),
                      "+f"(c[mt][nt][2]), "+f"(c[mt][nt][3])
                    : "r"(a[mt][0]), "r"(a[mt][1]), "r"(a[mt][2]), "r"(a[mt][3]),
                      "r"(b0), "r"(b1));
            }
        }
    }

    // fold bias into accumulators (cols depend on nt/tg, same for both rows)
#pragma unroll
    for (int nt = 0; nt < 4; nt++) {
        float bv0 = bias[n_base + nt * 8 + tg * 2];
        float bv1 = bias[n_base + nt * 8 + tg * 2 + 1];
#pragma unroll
        for (int mt = 0; mt < 2; mt++) {
            c[mt][nt][0] += bv0; c[mt][nt][1] += bv1;
            c[mt][nt][2] += bv0; c[mt][nt][3] += bv1;
        }
    }

    // phase 1: per-row warp max + target capture
#pragma unroll
    for (int slot = 0; slot < 4; slot++) {
        int mt = slot >> 1, hi = slot & 1;
        int rl = wm * 32 + mt * 16 + gid + hi * 8;
        float ml = -1e30f;
#pragma unroll
        for (int nt = 0; nt < 4; nt++) {
            ml = fmaxf(ml, c[mt][nt][hi * 2]);
            ml = fmaxf(ml, c[mt][nt][hi * 2 + 1]);
        }
        ml = fmaxf(ml, __shfl_xor_sync(0xffffffffu, ml, 1));
        ml = fmaxf(ml, __shfl_xor_sync(0xffffffffu, ml, 2));
        if (tg == 0) sMax[wn][rl] = ml;

        int tl = sTgt[rl] - n0;
        if (tl >= 0 && tl < 64 && (tl >> 5) == wn) {
            int ntt = (tl & 31) >> 3;
            int tgt_tg = (tl & 7) >> 1;
            int qt = tl & 1;
            if (tg == tgt_tg) {
                float val = 0.f;
#pragma unroll
                for (int nt = 0; nt < 4; nt++)
                    if (nt == ntt) val = c[mt][nt][hi * 2 + qt];
                g_tgt[rowbase + rl] = val;
            }
        }
    }
    __syncthreads();

    // phase 2: per-row warp sumexp relative to block row max
#pragma unroll
    for (int slot = 0; slot < 4; slot++) {
        int mt = slot >> 1, hi = slot & 1;
        int rl = wm * 32 + mt * 16 + gid + hi * 8;
        float M = fmaxf(sMax[0][rl], sMax[1][rl]);
        float sl = 0.f;
#pragma unroll
        for (int nt = 0; nt < 4; nt++) {
            sl += __expf(c[mt][nt][hi * 2] - M);
            sl += __expf(c[mt][nt][hi * 2 + 1] - M);
        }
        sl += __shfl_xor_sync(0xffffffffu, sl, 1);
        sl += __shfl_xor_sync(0xffffffffu, sl, 2);
        if (tg == 0) sSum[wn][rl] = sl;
    }
    __syncthreads();

    if (tid < 128) {
        float M = fmaxf(sMax[0][tid], sMax[1][tid]);
        g_part[(size_t)(rowbase + tid) * NBLKS + nblk] =
            make_float2(M, sSum[0][tid] + sSum[1][tid]);
    }
}

// ---------------- combine partials -> per-row NLL ----------------------------
__global__ void k_nll2() {
    int r = blockIdx.x, t = threadIdx.x;
    const float2* pp = g_part + (size_t)r * NBLKS;

    float m = -1e30f, s = 0.0f;
    for (int i = t; i < NBLKS; i += 256) {
        float2 p = pp[i];
        if (p.x > m) { s = s * __expf(m - p.x) + p.y; m = p.x; }
        else s += p.y * __expf(p.x - m);
    }
    __shared__ float sm_[256], ss_[256];
    sm_[t] = m; ss_[t] = s; __syncthreads();
    for (int k = 128; k > 0; k >>= 1) {
        if (t < k) {
            float m2 = sm_[t + k], s2 = ss_[t + k];
            float M = fmaxf(sm_[t], m2);
            ss_[t] = ss_[t] * __expf(sm_[t] - M) + s2 * __expf(m2 - M);
            sm_[t] = M;
        }
        __syncthreads();
    }
    if (t == 0) g_rownll[r] = sm_[0] + logf(ss_[0]) - g_tgt[r];
}

__global__ void k_mean(float* __restrict__ out) {
    __shared__ float red[256];
    int t = threadIdx.x;
    float s = 0.0f;
    for (int i = t; i < BT; i += 256) s += g_rownll[i];
    red[t] = s; __syncthreads();
    for (int k = 128; k > 0; k >>= 1) {
        if (t < k) red[t] += red[t + k];
        __syncthreads();
    }
    if (t == 0) out[0] = red[0] / (float)BT;
}

// ---------------- launch -----------------------------------------------------
extern "C" void kernel_launch(void* const* d_in, const int* in_sizes, int n_in,
                              void* d_out, int out_size) {
    const int*   src      = (const int*)  d_in[0];
    const int*   src_len  = (const int*)  d_in[1];
    const int*   trg_in   = (const int*)  d_in[2];
    const int*   trg_out  = (const int*)  d_in[3];
    const float* src_emb  = (const float*)d_in[4];
    const float* trg_emb  = (const float*)d_in[5];
    const float* enc_Wih  = (const float*)d_in[6];
    const float* enc_Whh  = (const float*)d_in[7];
    const float* enc_bih  = (const float*)d_in[8];
    const float* enc_bhh  = (const float*)d_in[9];
    const float* dec_Wi   = (const float*)d_in[10];
    const float* dec_bi   = (const float*)d_in[11];
    const float* dec_Wh   = (const float*)d_in[12];
    const float* dec_bh   = (const float*)d_in[13];
    const float* dec_Wp   = (const float*)d_in[14];
    const float* dec_bp   = (const float*)d_in[15];
    const float* out_W    = (const float*)d_in[16];
    const float* out_b    = (const float*)d_in[17];
    float* out = (float*)d_out;

    const int SMEMB = (12 * 520 + 32 * 516 + 4 * 384 + 384) * 4;   // 98688 B
    cudaFuncSetAttribute(k_recur<SLEN, false>,
                         cudaFuncAttributeMaxDynamicSharedMemorySize, SMEMB);
    cudaFuncSetAttribute(k_recur<TLEN, true>,
                         cudaFuncAttributeMaxDynamicSharedMemorySize, SMEMB);

    k_reset_bars<<<1, 1>>>();
    k_zero_h0<<<(BATCH * HID + 255) / 256, 256>>>();

    // gx = emb(src) @ Wih^T + bih   [4096 x 1536]
    k_big_gemm<<<dim3(G3 / 64, SB / 64), 256>>>(src_emb, src, SLEN, SB, EMB,
                                                enc_Wih, enc_bih, 0, 0);
    // gi = emb(trg) @ Wi^T + bi     [2048 x 1536]
    k_big_gemm<<<dim3(G3 / 64, BT / 64), 256>>>(trg_emb, trg_in, TLEN, BT, EMB,
                                                dec_Wi, dec_bi, 1, 0);
    // bf16 weights for output projection
    k_conv_w<<<(VOC * HID / 2 + 255) / 256, 256>>>(out_W);

    // encoder: all 128 steps in one persistent kernel
    k_recur<SLEN, false><<<RNBLK, 384, SMEMB>>>(enc_Whh, enc_bhh, src_len);

    // p = ctx @ Wp^T + bp  (ctx = final encoder h in g_h[0])
    k_big_gemm<<<dim3(G3 / 64, 1), 256>>>(nullptr, nullptr, 0, BATCH, HID,
                                          dec_Wp, dec_bp, 2, 1);

    // decoder: all 64 steps in one persistent kernel (writes g_hb bf16)
    k_recur<TLEN, true><<<RNBLK, 384, SMEMB>>>(dec_Wh, dec_bh, nullptr);

    // output projection + fused partial logsumexp, then combine + mean
    k_out_gemm<<<dim3(NBLKS, BT / 128), 256>>>(out_b, trg_out);
    k_nll2<<<BT, 256>>>();
    k_mean<<<1, 256>>>(out);
}

// round 6
// speedup vs baseline: 2.7552x; 1.0082x over previous
#include <cuda_runtime.h>
#include <cuda_bf16.h>
#include <cstdint>

#define BATCH 32
#define SLEN  128
#define TLEN  64
#define VOC   32000
#define EMB   256
#define HID   512
#define G3    1536            // 3*HID
#define BT    (BATCH*TLEN)    // 2048 decoder rows
#define SB    (SLEN*BATCH)    // 4096 encoder rows
#define RNBLK 128             // persistent recurrence blocks (<=148 SMs)
#define NBLKS (VOC/64)        // 500 n-blocks in output projection

// ---------------- scratch (device globals; no allocation allowed) ----------
__device__ float g_gx  [SB*G3];               // [s][b][3H]
__device__ float g_gi  [BT*G3];               // [t][b][3H]
__device__ float g_p   [BATCH*G3];            // ctx @ Wp^T + bp
__device__ float g_h   [2][BATCH*HID];        // hidden ping-pong (enc then dec)
__device__ __nv_bfloat16 g_hb[BT*HID];        // bf16 decoder outputs, row = b*T+t
__device__ __nv_bfloat16 g_Wb[VOC*HID];       // bf16 copy of out_W
__device__ float2 g_part[(size_t)BT*NBLKS];   // per (row, nblk) {max, sumexp}
__device__ float g_tgt[BT];                   // target logit per row (with bias)
__device__ float g_rownll[BT];
__device__ unsigned g_barE, g_barD;

__device__ __forceinline__ float sigf(float x) { return 1.0f / (1.0f + __expf(-x)); }

__global__ void k_reset_bars() { g_barE = 0; g_barD = 0; }

__global__ void k_zero_h0() {
    int i = blockIdx.x * 256 + threadIdx.x;
    if (i < BATCH * HID) g_h[0][i] = 0.0f;
}

// ---------------- input GEMM:  out[m][n] = A_row(m) . W[n][:] + bias[n] -----
__global__ void k_big_gemm(const float* __restrict__ Asrc,
                           const int* __restrict__ ids, int ids_len,
                           int rows, int K,
                           const float* __restrict__ W,
                           const float* __restrict__ bias,
                           int outsel, int a_from_ctx) {
    __shared__ __align__(16) float As[16][72];   // [kk][m]
    __shared__ __align__(16) float Bs[16][72];   // [kk][n]
    __shared__ int sIds[64];

    float* out = (outsel == 0) ? g_gx : (outsel == 1) ? g_gi : g_p;
    const float* Abase = a_from_ctx ? g_h[0] : Asrc;

    int tid = threadIdx.x;                // 256 threads
    int m0 = blockIdx.y * 64, n0 = blockIdx.x * 64;
    int ty = tid / 16, tx = tid % 16;

    if (ids) {
        for (int i = tid; i < 64; i += 256) {
            int m = m0 + i;
            sIds[i] = (m < rows) ? ids[(m % BATCH) * ids_len + (m / BATCH)] : 0;
        }
        __syncthreads();
    }

    float acc[4][4];
#pragma unroll
    for (int i = 0; i < 4; i++)
#pragma unroll
        for (int j = 0; j < 4; j++) acc[i][j] = 0.0f;

    for (int k0 = 0; k0 < K; k0 += 16) {
        for (int i = tid; i < 1024; i += 256) {
            int r = i / 16, kk = i % 16;
            int m = m0 + r;
            float v = 0.0f;
            if (m < rows) {
                const float* ap = ids ? (Abase + (size_t)sIds[r] * K)
                                      : (Abase + (size_t)m * K);
                v = ap[k0 + kk];
            }
            As[kk][r] = v;
        }
        for (int i = tid; i < 1024; i += 256) {
            int n = i / 16, kk = i % 16;
            Bs[kk][n] = W[(size_t)(n0 + n) * K + k0 + kk];
        }
        __syncthreads();
#pragma unroll
        for (int kk = 0; kk < 16; kk++) {
            float4 a4 = *(const float4*)&As[kk][ty * 4];
            float4 b4 = *(const float4*)&Bs[kk][tx * 4];
            float a[4] = {a4.x, a4.y, a4.z, a4.w};
            float b[4] = {b4.x, b4.y, b4.z, b4.w};
#pragma unroll
            for (int i = 0; i < 4; i++)
#pragma unroll
                for (int j = 0; j < 4; j++) acc[i][j] += a[i] * b[j];
        }
        __syncthreads();
    }

#pragma unroll
    for (int i = 0; i < 4; i++) {
        int m = m0 + ty * 4 + i;
        if (m >= rows) continue;
#pragma unroll
        for (int j = 0; j < 4; j++) {
            int n = n0 + tx * 4 + j;
            out[(size_t)m * G3 + n] = acc[i][j] + bias[n];
        }
    }
}

// ---------------- persistent recurrence v2 ----------------------------------
// 128 blocks x 384 thr (12 warps). Block owns 4 h-cols (12 gate cols).
// Dot: warp = (col-group cw of 4 cols, k-chunk kc of 128); lane = (cl, o),
// computes 4 batch outputs (o, o+8, o+16, o+24). Partials reduced via smem.
// Grid barrier: single-thread release/acquire atomics.
template<int STEPS, bool DEC>
__global__ void __launch_bounds__(384, 1)
k_recur(const float* __restrict__ Wrec,   // [G3][HID] row-major
        const float* __restrict__ brec,   // [G3]
        const int* __restrict__ src_len)  // encoder only
{
    extern __shared__ float sm[];
    float* Wsm = sm;                       // 12*520
    float* hsm = Wsm + 12 * 520;           // 32*516
    float* red = hsm + 32 * 516;           // 4*384 partials
    float* ghm = red + 4 * 384;            // 384 reduced gates

    const int t = threadIdx.x;
    const int j0 = blockIdx.x * 4;

    // cache weight slice (12 gate rows x 512) in smem, padded to 520
    for (int i = t; i < 12 * 512; i += 384) {
        int gc = i >> 9, k = i & 511;
        Wsm[gc * 520 + k] = Wrec[(size_t)((gc >> 2) * 512 + j0 + (gc & 3)) * 512 + k];
    }

    // dot-role constants
    const int w  = t >> 5;                 // warp 0..11
    const int kc = w & 3;                  // k-chunk
    const int cw = w >> 2;                 // col-group 0..2
    const int lane = t & 31;
    const int cl = lane >> 3, o = lane & 7;
    const int gc_d = cw * 4 + cl;

    // reduce-role constants
    const int gc_r = t >> 5;               // 0..11
    const int b_r  = t & 31;
    const float biasr = brec[(gc_r >> 2) * 512 + j0 + (gc_r & 3)];

    // combine-role constants (t < 128)
    const int hc = t >> 5, bc = t & 31;    // valid when t<128
    const int jc = j0 + hc;
    float p0 = 0.f, p1 = 0.f, p2 = 0.f;
    int slen = 0;
    if (t < 128) {
        if (DEC) {
            p0 = g_p[bc * G3 + jc];
            p1 = g_p[bc * G3 + 512 + jc];
            p2 = g_p[bc * G3 + 1024 + jc];
        } else {
            slen = src_len[bc];
        }
    }
    __syncthreads();

    unsigned* bar = DEC ? &g_barD : &g_barE;
    const float* gbase = DEC ? g_gi : g_gx;

    for (int s = 0; s < STEPS; s++) {
        const float* hprev = g_h[s & 1];
        float* hnext = g_h[(s + 1) & 1];

        // prefetch this step's input-gate values (used in combine)
        float gx0 = 0.f, gx1 = 0.f, gx2 = 0.f;
        if (t < 128) {
            const float* gr = gbase + ((size_t)s * BATCH + bc) * G3;
            gx0 = gr[jc]; gx1 = gr[512 + jc]; gx2 = gr[1024 + jc];
        }

        // stage h[32][512] to smem
        for (int f = t; f < 4096; f += 384) {
            int b = f >> 7, kq = f & 127;
            float4 v = __ldcg((const float4*)(hprev + b * 512 + kq * 4));
            *(float4*)(hsm + b * 516 + kq * 4) = v;
        }
        __syncthreads();

        // dot partials: 4 batches per lane over a 128-k chunk
        {
            const float* wp = Wsm + gc_d * 520 + kc * 128;
            const float* h0 = hsm + (o     ) * 516 + kc * 128;
            const float* h1 = hsm + (o +  8) * 516 + kc * 128;
            const float* h2 = hsm + (o + 16) * 516 + kc * 128;
            const float* h3 = hsm + (o + 24) * 516 + kc * 128;
            float a0 = 0.f, a1 = 0.f, a2 = 0.f, a3 = 0.f;
#pragma unroll 8
            for (int k = 0; k < 128; k += 4) {
                float4 wv = *(const float4*)(wp + k);
                float4 v0 = *(const float4*)(h0 + k);
                float4 v1 = *(const float4*)(h1 + k);
                float4 v2 = *(const float4*)(h2 + k);
                float4 v3 = *(const float4*)(h3 + k);
                a0 += wv.x * v0.x + wv.y * v0.y + wv.z * v0.z + wv.w * v0.w;
                a1 += wv.x * v1.x + wv.y * v1.y + wv.z * v1.z + wv.w * v1.w;
                a2 += wv.x * v2.x + wv.y * v2.y + wv.z * v2.z + wv.w * v2.w;
                a3 += wv.x * v3.x + wv.y * v3.y + wv.z * v3.z + wv.w * v3.w;
            }
            float* rp = red + kc * 384 + gc_d * 32;
            rp[o] = a0; rp[o + 8] = a1; rp[o + 16] = a2; rp[o + 24] = a3;
        }
        __syncthreads();

        // reduce 4 k-chunks + bias
        ghm[gc_r * 32 + b_r] = red[gc_r * 32 + b_r] + red[384 + gc_r * 32 + b_r]
                             + red[768 + gc_r * 32 + b_r] + red[1152 + gc_r * 32 + b_r]
                             + biasr;
        __syncthreads();

        // combine gates + write new h
        if (t < 128) {
            float ghr = ghm[hc * 32 + bc];
            float ghz = ghm[(4 + hc) * 32 + bc];
            float ghn = ghm[(8 + hc) * 32 + bc];
            float hold = hsm[bc * 516 + jc];
            float hy;
            if (DEC) {
                float r  = sigf(gx0 + ghr + p0);
                float ig = sigf(gx1 + ghz + p1);
                float nn = tanhf(gx2 + r * ghn + p2);
                hy = nn + ig * (hold - nn);
                g_hb[((size_t)bc * TLEN + s) * HID + jc] = __float2bfloat16(hy);
            } else {
                float r  = sigf(gx0 + ghr);
                float z  = sigf(gx1 + ghz);
                float nn = tanhf(gx2 + r * ghn);
                float hn = (1.0f - z) * nn + z * hold;
                hy = (s < slen) ? hn : hold;
            }
            __stcg(hnext + bc * 512 + jc, hy);
        }

        // grid barrier (release/acquire, single thread)
        if (s + 1 < STEPS) {
            __syncthreads();
            if (t == 0) {
                asm volatile("red.release.gpu.global.add.u32 [%0], %1;"
                             :: "l"(bar), "r"(1u) : "memory");
                unsigned target = (unsigned)(s + 1) * RNBLK;
                unsigned v;
                do {
                    asm volatile("ld.acquire.gpu.global.u32 %0, [%1];"
                                 : "=r"(v) : "l"(bar) : "memory");
                    if (v >= target) break;
                    __nanosleep(32);
                } while (true);
            }
            __syncthreads();
        }
    }
}

// ---------------- fp32 -> bf16 weight conversion -----------------------------
__global__ void k_conv_w(const float* __restrict__ w) {
    int i = blockIdx.x * 256 + threadIdx.x;
    if (i < VOC * HID / 2) {
        float2 a = ((const float2*)w)[i];
        ((__nv_bfloat162*)g_Wb)[i] = __floats2bfloat162_rn(a.x, a.y);
    }
}

// ---------------- output projection + fused partial logsumexp ----------------
// C tile 128m x 64n per block; emits per-row {max,sumexp} partial + target logit.
__global__ void __launch_bounds__(256) k_out_gemm(const float* __restrict__ bias,
                                                  const int* __restrict__ trg_out) {
    __shared__ int   sTgt[128];
    __shared__ float sMax[2][128];
    __shared__ float sSum[2][128];

    int tid = threadIdx.x;
    int lane = tid & 31, warp = tid >> 5;
    int wm = warp >> 1, wn = warp & 1;
    int nblk = blockIdx.x, mblk = blockIdx.y;
    int rowbase = mblk * 128, n0 = nblk * 64;
    int m_base = rowbase + wm * 32;
    int n_base = n0 + wn * 32;
    int gid = lane >> 2, tg = lane & 3;

    for (int i = tid; i < 128; i += 256) sTgt[i] = trg_out[rowbase + i];
    __syncthreads();

    float c[2][4][4];
#pragma unroll
    for (int mt = 0; mt < 2; mt++)
#pragma unroll
        for (int nt = 0; nt < 4; nt++)
#pragma unroll
            for (int q = 0; q < 4; q++) c[mt][nt][q] = 0.0f;

    for (int k0 = 0; k0 < HID; k0 += 16) {
        uint32_t a[2][4];
#pragma unroll
        for (int mt = 0; mt < 2; mt++) {
            const __nv_bfloat16* ap =
                g_hb + (size_t)(m_base + mt * 16 + gid) * HID + k0 + tg * 2;
            a[mt][0] = *(const uint32_t*)(ap);
            a[mt][1] = *(const uint32_t*)(ap + 8 * HID);
            a[mt][2] = *(const uint32_t*)(ap + 8);
            a[mt][3] = *(const uint32_t*)(ap + 8 * HID + 8);
        }
#pragma unroll
        for (int nt = 0; nt < 4; nt++) {
            const __nv_bfloat16* bp =
                g_Wb + (size_t)(n_base + nt * 8 + gid) * HID + k0 + tg * 2;
            uint32_t b0 = *(const uint32_t*)(bp);
            uint32_t b1 = *(const uint32_t*)(bp + 8);
#pragma unroll
            for (int mt = 0; mt < 2; mt++) {
                asm volatile(
                    "mma.sync.aligned.m16n8k16.row.col.f32.bf16.bf16.f32 "
                    "{%0,%1,%2,%3}, {%4,%5,%6,%7}, {%8,%9}, {%0,%1,%2,%3};"
                    : "+f"(c[mt][nt][0]), "+f"(c[mt][nt][1]),
                      "+f"(c[mt][nt][2]), "+f"(c[mt][nt][3])
                    : "r"(a[mt][0]), "r"(a[mt][1]), "r"(a[mt][2]), "r"(a[mt][3]),
                      "r"(b0), "r"(b1));
            }
        }
    }

    // fold bias into accumulators (cols depend on nt/tg, same for both rows)
#pragma unroll
    for (int nt = 0; nt < 4; nt++) {
        float bv0 = bias[n_base + nt * 8 + tg * 2];
        float bv1 = bias[n_base + nt * 8 + tg * 2 + 1];
#pragma unroll
        for (int mt = 0; mt < 2; mt++) {
            c[mt][nt][0] += bv0; c[mt][nt][1] += bv1;
            c[mt][nt][2] += bv0; c[mt][nt][3] += bv1;
        }
    }

    // phase 1: per-row warp max + target capture
#pragma unroll
    for (int slot = 0; slot < 4; slot++) {
        int mt = slot >> 1, hi = slot & 1;
        int rl = wm * 32 + mt * 16 + gid + hi * 8;
        float ml = -1e30f;
#pragma unroll
        for (int nt = 0; nt < 4; nt++) {
            ml = fmaxf(ml, c[mt][nt][hi * 2]);
            ml = fmaxf(ml, c[mt][nt][hi * 2 + 1]);
        }
        ml = fmaxf(ml, __shfl_xor_sync(0xffffffffu, ml, 1));
        ml = fmaxf(ml, __shfl_xor_sync(0xffffffffu, ml, 2));
        if (tg == 0) sMax[wn][rl] = ml;

        int tl = sTgt[rl] - n0;
        if (tl >= 0 && tl < 64 && (tl >> 5) == wn) {
            int ntt = (tl & 31) >> 3;
            int tgt_tg = (tl & 7) >> 1;
            int qt = tl & 1;
            if (tg == tgt_tg) {
                float val = 0.f;
#pragma unroll
                for (int nt = 0; nt < 4; nt++)
                    if (nt == ntt) val = c[mt][nt][hi * 2 + qt];
                g_tgt[rowbase + rl] = val;
            }
        }
    }
    __syncthreads();

    // phase 2: per-row warp sumexp relative to block row max
#pragma unroll
    for (int slot = 0; slot < 4; slot++) {
        int mt = slot >> 1, hi = slot & 1;
        int rl = wm * 32 + mt * 16 + gid + hi * 8;
        float M = fmaxf(sMax[0][rl], sMax[1][rl]);
        float sl = 0.f;
#pragma unroll
        for (int nt = 0; nt < 4; nt++) {
            sl += __expf(c[mt][nt][hi * 2] - M);
            sl += __expf(c[mt][nt][hi * 2 + 1] - M);
        }
        sl += __shfl_xor_sync(0xffffffffu, sl, 1);
        sl += __shfl_xor_sync(0xffffffffu, sl, 2);
        if (tg == 0) sSum[wn][rl] = sl;
    }
    __syncthreads();

    if (tid < 128) {
        float M = fmaxf(sMax[0][tid], sMax[1][tid]);
        g_part[(size_t)(rowbase + tid) * NBLKS + nblk] =
            make_float2(M, sSum[0][tid] + sSum[1][tid]);
    }
}

// ---------------- combine partials -> per-row NLL ----------------------------
__global__ void k_nll2() {
    int r = blockIdx.x, t = threadIdx.x;
    const float2* pp = g_part + (size_t)r * NBLKS;

    float m = -1e30f, s = 0.0f;
    for (int i = t; i < NBLKS; i += 256) {
        float2 p = pp[i];
        if (p.x > m) { s = s * __expf(m - p.x) + p.y; m = p.x; }
        else s += p.y * __expf(p.x - m);
    }
    __shared__ float sm_[256], ss_[256];
    sm_[t] = m; ss_[t] = s; __syncthreads();
    for (int k = 128; k > 0; k >>= 1) {
        if (t < k) {
            float m2 = sm_[t + k], s2 = ss_[t + k];
            float M = fmaxf(sm_[t], m2);
            ss_[t] = ss_[t] * __expf(sm_[t] - M) + s2 * __expf(m2 - M);
            sm_[t] = M;
        }
        __syncthreads();
    }
    if (t == 0) g_rownll[r] = sm_[0] + logf(ss_[0]) - g_tgt[r];
}

__global__ void k_mean(float* __restrict__ out) {
    __shared__ float red[256];
    int t = threadIdx.x;
    float s = 0.0f;
    for (int i = t; i < BT; i += 256) s += g_rownll[i];
    red[t] = s; __syncthreads();
    for (int k = 128; k > 0; k >>= 1) {
        if (t < k) red[t] += red[t + k];
        __syncthreads();
    }
    if (t == 0) out[0] = red[0] / (float)BT;
}

// ---------------- launch -----------------------------------------------------
extern "C" void kernel_launch(void* const* d_in, const int* in_sizes, int n_in,
                              void* d_out, int out_size) {
    const int*   src      = (const int*)  d_in[0];
    const int*   src_len  = (const int*)  d_in[1];
    const int*   trg_in   = (const int*)  d_in[2];
    const int*   trg_out  = (const int*)  d_in[3];
    const float* src_emb  = (const float*)d_in[4];
    const float* trg_emb  = (const float*)d_in[5];
    const float* enc_Wih  = (const float*)d_in[6];
    const float* enc_Whh  = (const float*)d_in[7];
    const float* enc_bih  = (const float*)d_in[8];
    const float* enc_bhh  = (const float*)d_in[9];
    const float* dec_Wi   = (const float*)d_in[10];
    const float* dec_bi   = (const float*)d_in[11];
    const float* dec_Wh   = (const float*)d_in[12];
    const float* dec_bh   = (const float*)d_in[13];
    const float* dec_Wp   = (const float*)d_in[14];
    const float* dec_bp   = (const float*)d_in[15];
    const float* out_W    = (const float*)d_in[16];
    const float* out_b    = (const float*)d_in[17];
    float* out = (float*)d_out;

    const int SMEMB = (12 * 520 + 32 * 516 + 4 * 384 + 384) * 4;   // 98688 B
    cudaFuncSetAttribute(k_recur<SLEN, false>,
                         cudaFuncAttributeMaxDynamicSharedMemorySize, SMEMB);
    cudaFuncSetAttribute(k_recur<TLEN, true>,
                         cudaFuncAttributeMaxDynamicSharedMemorySize, SMEMB);

    k_reset_bars<<<1, 1>>>();
    k_zero_h0<<<(BATCH * HID + 255) / 256, 256>>>();

    // gx = emb(src) @ Wih^T + bih   [4096 x 1536]
    k_big_gemm<<<dim3(G3 / 64, SB / 64), 256>>>(src_emb, src, SLEN, SB, EMB,
                                                enc_Wih, enc_bih, 0, 0);
    // gi = emb(trg) @ Wi^T + bi     [2048 x 1536]
    k_big_gemm<<<dim3(G3 / 64, BT / 64), 256>>>(trg_emb, trg_in, TLEN, BT, EMB,
                                                dec_Wi, dec_bi, 1, 0);
    // bf16 weights for output projection
    k_conv_w<<<(VOC * HID / 2 + 255) / 256, 256>>>(out_W);

    // encoder: all 128 steps in one persistent kernel
    k_recur<SLEN, false><<<RNBLK, 384, SMEMB>>>(enc_Whh, enc_bhh, src_len);

    // p = ctx @ Wp^T + bp  (ctx = final encoder h in g_h[0])
    k_big_gemm<<<dim3(G3 / 64, 1), 256>>>(nullptr, nullptr, 0, BATCH, HID,
                                          dec_Wp, dec_bp, 2, 1);

    // decoder: all 64 steps in one persistent kernel (writes g_hb bf16)
    k_recur<TLEN, true><<<RNBLK, 384, SMEMB>>>(dec_Wh, dec_bh, nullptr);

    // output projection + fused partial logsumexp, then combine + mean
    k_out_gemm<<<dim3(NBLKS, BT / 128), 256>>>(out_b, trg_out);
    k_nll2<<<BT, 256>>>();
    k_mean<<<1, 256>>>(out);
}